// round 1
// baseline (speedup 1.0000x reference)
#include <cuda_runtime.h>
#include <cuda_bf16.h>
#include <math.h>

// ---------------------------------------------------------------------------
// Problem shapes (fixed)
// ---------------------------------------------------------------------------
#define BATCH 4
#define DIM 192
#define HEADS 8
#define HDIM 24          // DIM / HEADS
#define HH 256
#define WW 256
#define HWN 65536        // HH*WW
#define QKV_CH 576       // 3*DIM

// ---------------------------------------------------------------------------
// Scratch (device globals: allocation-free rule)
// ---------------------------------------------------------------------------
__device__ float g_qkv[(size_t)BATCH * QKV_CH * HWN];          // 604 MB, post-1x1-conv
__device__ float g_v[(size_t)BATCH * DIM * HWN];               // 201 MB, post-dwconv v
__device__ float g_spart[(size_t)BATCH * HEADS * 512 * 624];   // per-block Gram partials
__device__ float g_sred[BATCH * HEADS * 624];                  // reduced Gram + sq + sk
__device__ float g_attn[BATCH * HEADS * HDIM * HDIM];          // softmaxed attention
__device__ float g_M[BATCH * DIM * DIM];                       // P * blockdiag(attn)

// ---------------------------------------------------------------------------
// K1 / K7: classic register-tiled SGEMM  C[O,N] = A[O,K] * B[K,N]
// BM=64, BN=128, BK=16, 256 threads, 4x8 per-thread tile.
// O divisible by 64, N divisible by 128, K divisible by 16 (192 -> 12 iters).
// ---------------------------------------------------------------------------
__global__ __launch_bounds__(256)
void sgemm_k(const float* __restrict__ A, const float* __restrict__ B,
             float* __restrict__ C, int K, int N,
             size_t sA, size_t sB, size_t sC)
{
    A += (size_t)blockIdx.z * sA;
    B += (size_t)blockIdx.z * sB;
    C += (size_t)blockIdx.z * sC;

    __shared__ float As[16][68];    // [k][m], padded
    __shared__ float Bs[16][128];   // [k][n]

    const int tid  = threadIdx.x;
    const int m0   = blockIdx.y * 64;
    const int n0   = blockIdx.x * 128;
    const int arow = tid >> 2;             // 0..63
    const int acol = (tid & 3) * 4;        // 0,4,8,12
    const int brow = tid >> 5;             // 0..7
    const int bcol = (tid & 31) * 4;       // 0..124
    const int ty   = tid >> 4;             // 0..15 -> m = ty*4
    const int tx   = tid & 15;             // 0..15 -> n = tx*8

    float acc[4][8];
#pragma unroll
    for (int i = 0; i < 4; i++)
#pragma unroll
        for (int j = 0; j < 8; j++) acc[i][j] = 0.f;

    const float* Aptr = A + (size_t)(m0 + arow) * K + acol;
    const float* Bptr = B + (size_t)brow * N + n0 + bcol;

    for (int k0 = 0; k0 < K; k0 += 16) {
        float4 av = *(const float4*)(Aptr + k0);
        float4 b0 = *(const float4*)(Bptr + (size_t)k0 * N);
        float4 b1 = *(const float4*)(Bptr + (size_t)(k0 + 8) * N);

        As[acol + 0][arow] = av.x;
        As[acol + 1][arow] = av.y;
        As[acol + 2][arow] = av.z;
        As[acol + 3][arow] = av.w;
        *(float4*)&Bs[brow][bcol]     = b0;
        *(float4*)&Bs[brow + 8][bcol] = b1;
        __syncthreads();

#pragma unroll
        for (int k = 0; k < 16; k++) {
            float a[4], bb[8];
            *(float4*)a        = *(const float4*)&As[k][ty * 4];
            *(float4*)&bb[0]   = *(const float4*)&Bs[k][tx * 8];
            *(float4*)&bb[4]   = *(const float4*)&Bs[k][tx * 8 + 4];
#pragma unroll
            for (int i = 0; i < 4; i++)
#pragma unroll
                for (int j = 0; j < 8; j++)
                    acc[i][j] = fmaf(a[i], bb[j], acc[i][j]);
        }
        __syncthreads();
    }

#pragma unroll
    for (int i = 0; i < 4; i++) {
        float4 o0 = make_float4(acc[i][0], acc[i][1], acc[i][2], acc[i][3]);
        float4 o1 = make_float4(acc[i][4], acc[i][5], acc[i][6], acc[i][7]);
        size_t off = (size_t)(m0 + ty * 4 + i) * N + n0 + tx * 8;
        *(float4*)&C[off]     = o0;
        *(float4*)&C[off + 4] = o1;
    }
}

// ---------------------------------------------------------------------------
// depthwise 3x3, SAME padding, cross-correlation (matches lax/torch conv)
// ---------------------------------------------------------------------------
__device__ __forceinline__ float dw3x3(const float* __restrict__ in,
                                       const float* __restrict__ w9,
                                       int y, int x)
{
    float s = 0.f;
#pragma unroll
    for (int dy = -1; dy <= 1; dy++) {
        int yy = y + dy;
        if (yy < 0 || yy > HH - 1) continue;
#pragma unroll
        for (int dx = -1; dx <= 1; dx++) {
            int xx = x + dx;
            if (xx < 0 || xx > WW - 1) continue;
            s = fmaf(w9[(dy + 1) * 3 + (dx + 1)], in[yy * WW + xx], s);
        }
    }
    return s;
}

// ---------------------------------------------------------------------------
// K2: fused dwconv (q,k channels of one head) + Gram partials + norms.
// Grid: (512 half-rows, 8 heads, 4 batch).  Block: 192 threads.
// Each block: 48 channels x 128 pixels dwconv into smem, then
//   threads 0..143: 2x2 tiles of the 24x24 Gram
//   threads 144..167: sum q^2 per d;  168..191: sum k^2 per e.
// Deterministic (no atomics): partials go to g_spart.
// ---------------------------------------------------------------------------
__global__ __launch_bounds__(192)
void dwgram_k(const float* __restrict__ qkv, const float* __restrict__ dww,
              float* __restrict__ spart)
{
    __shared__ float qs[24][132];
    __shared__ float ks[24][132];

    const int b = blockIdx.z, h = blockIdx.y;
    const int y = blockIdx.x >> 1;
    const int x0 = (blockIdx.x & 1) * 128;
    const int tid = threadIdx.x;

    for (int idx = tid; idx < 48 * 128; idx += 192) {
        int c = idx >> 7;              // 0..47
        int x = idx & 127;
        int ch = (c < 24) ? (h * 24 + c) : (192 + h * 24 + (c - 24));
        const float* in = qkv + ((size_t)(b * QKV_CH + ch) << 16);
        float v = dw3x3(in, dww + ch * 9, y, x0 + x);
        if (c < 24) qs[c][x] = v;
        else        ks[c - 24][x] = v;
    }
    __syncthreads();

    float* out = spart + ((size_t)(b * HEADS + h) * 512 + blockIdx.x) * 624;

    if (tid < 144) {
        int d = (tid / 12) * 2, e = (tid % 12) * 2;
        float a00 = 0, a01 = 0, a10 = 0, a11 = 0;
#pragma unroll 4
        for (int n = 0; n < 128; n++) {
            float q0 = qs[d][n],     q1 = qs[d + 1][n];
            float k0 = ks[e][n],     k1 = ks[e + 1][n];
            a00 = fmaf(q0, k0, a00); a01 = fmaf(q0, k1, a01);
            a10 = fmaf(q1, k0, a10); a11 = fmaf(q1, k1, a11);
        }
        out[d * 24 + e]           = a00;
        out[d * 24 + e + 1]       = a01;
        out[(d + 1) * 24 + e]     = a10;
        out[(d + 1) * 24 + e + 1] = a11;
    } else if (tid < 168) {
        int d = tid - 144;
        float s = 0;
#pragma unroll 4
        for (int n = 0; n < 128; n++) { float q = qs[d][n]; s = fmaf(q, q, s); }
        out[576 + d] = s;
    } else {
        int e = tid - 168;
        float s = 0;
#pragma unroll 4
        for (int n = 0; n < 128; n++) { float q = ks[e][n]; s = fmaf(q, q, s); }
        out[600 + e] = s;
    }
}

// ---------------------------------------------------------------------------
// K3: dwconv for v channels -> g_v.  Grid (256 rows, 192 ch, 4 b), 256 thr.
// ---------------------------------------------------------------------------
__global__ __launch_bounds__(256)
void dwv_k(const float* __restrict__ qkv, const float* __restrict__ dww,
           float* __restrict__ v)
{
    const int b = blockIdx.z, c = blockIdx.y, y = blockIdx.x, x = threadIdx.x;
    const int ch = 384 + c;
    const float* in = qkv + ((size_t)(b * QKV_CH + ch) << 16);
    v[((size_t)(b * DIM + c) << 16) + y * WW + x] = dw3x3(in, dww + ch * 9, y, x);
}

// ---------------------------------------------------------------------------
// K4: reduce the 512 Gram partials per (b,head).  Grid 32, block 624.
// ---------------------------------------------------------------------------
__global__ __launch_bounds__(624)
void reduce_k(const float* __restrict__ spart, float* __restrict__ sred)
{
    const int bh = blockIdx.x;
    const int j  = threadIdx.x;
    const float* p = spart + (size_t)bh * 512 * 624 + j;
    float s = 0.f;
    for (int y = 0; y < 512; y++) s += p[(size_t)y * 624];
    sred[bh * 624 + j] = s;
}

// ---------------------------------------------------------------------------
// K5: softmax over the scaled Gram -> attn.  Grid 32, block 576.
// logit[d][e] = S[d][e] / (max(||q_d||,eps)*max(||k_e||,eps)) * tau[h]
// ---------------------------------------------------------------------------
__global__ __launch_bounds__(576)
void softmax_k(const float* __restrict__ sred, const float* __restrict__ temp,
               float* __restrict__ attn)
{
    const int bh = blockIdx.x;
    const int h  = bh & 7;
    const int t  = threadIdx.x;
    const int d  = t / 24, e = t % 24;

    __shared__ float lg[24][24];
    __shared__ float rmax[24], rsum[24];

    const float* S = sred + bh * 624;
    float nq = fmaxf(sqrtf(S[576 + d]), 1e-12f);
    float nk = fmaxf(sqrtf(S[600 + e]), 1e-12f);
    float l  = S[d * 24 + e] / (nq * nk) * temp[h];
    lg[d][e] = l;
    __syncthreads();

    if (e == 0) {
        float m = -1e30f;
        for (int j = 0; j < 24; j++) m = fmaxf(m, lg[d][j]);
        rmax[d] = m;
    }
    __syncthreads();
    float ex = expf(l - rmax[d]);
    lg[d][e] = ex;
    __syncthreads();
    if (e == 0) {
        float s = 0.f;
        for (int j = 0; j < 24; j++) s += lg[d][j];
        rsum[d] = s;
    }
    __syncthreads();
    attn[bh * 576 + d * 24 + e] = ex / rsum[d];
}

// ---------------------------------------------------------------------------
// K6: M[b] = P * blockdiag(attn[b]).  M[o][h*24+e] = sum_d P[o][h*24+d]*A[h][d][e]
// Grid 4, block 256.
// ---------------------------------------------------------------------------
__global__ __launch_bounds__(256)
void buildM_k(const float* __restrict__ attn, const float* __restrict__ P,
              float* __restrict__ M)
{
    const int b = blockIdx.x;
    __shared__ float at[HEADS * 576];
    for (int i = threadIdx.x; i < HEADS * 576; i += 256) at[i] = attn[b * HEADS * 576 + i];
    __syncthreads();

    for (int idx = threadIdx.x; idx < DIM * DIM; idx += 256) {
        int o = idx / DIM, c = idx % DIM;
        int hh = c / 24, e = c % 24;
        float s = 0.f;
#pragma unroll
        for (int d = 0; d < 24; d++)
            s = fmaf(P[o * DIM + hh * 24 + d], at[hh * 576 + d * 24 + e], s);
        M[(size_t)b * DIM * DIM + idx] = s;
    }
}

// ---------------------------------------------------------------------------
// launch
// ---------------------------------------------------------------------------
extern "C" void kernel_launch(void* const* d_in, const int* in_sizes, int n_in,
                              void* d_out, int out_size)
{
    const float* x      = (const float*)d_in[0];
    const float* qkv_w  = (const float*)d_in[1];
    const float* dw_w   = (const float*)d_in[2];
    const float* proj_w = (const float*)d_in[3];
    const float* temp   = (const float*)d_in[4];
    float* out = (float*)d_out;

    float *qkv_s, *v_s, *spart, *sred, *attn, *M;
    cudaGetSymbolAddress((void**)&qkv_s, g_qkv);
    cudaGetSymbolAddress((void**)&v_s,   g_v);
    cudaGetSymbolAddress((void**)&spart, g_spart);
    cudaGetSymbolAddress((void**)&sred,  g_sred);
    cudaGetSymbolAddress((void**)&attn,  g_attn);
    cudaGetSymbolAddress((void**)&M,     g_M);

    // K1: qkv = W_qkv @ x   (per batch: 576 x 192 x 65536)
    {
        dim3 grid(HWN / 128, QKV_CH / 64, BATCH);
        sgemm_k<<<grid, 256>>>(qkv_w, x, qkv_s, DIM, HWN,
                               (size_t)0, (size_t)DIM * HWN, (size_t)QKV_CH * HWN);
    }
    // K2: fused dwconv(q,k) + Gram partials
    {
        dim3 grid(512, HEADS, BATCH);
        dwgram_k<<<grid, 192>>>(qkv_s, dw_w, spart);
    }
    // K3: dwconv(v)
    {
        dim3 grid(HH, DIM, BATCH);
        dwv_k<<<grid, 256>>>(qkv_s, dw_w, v_s);
    }
    // K4: reduce Gram partials
    reduce_k<<<BATCH * HEADS, 624>>>(spart, sred);
    // K5: softmax
    softmax_k<<<BATCH * HEADS, 576>>>(sred, temp, attn);
    // K6: M = P * blockdiag(attn)
    buildM_k<<<BATCH, 256>>>(attn, proj_w, M);
    // K7: out = M @ V  (per batch: 192 x 192 x 65536) — fused attn*V + projection
    {
        dim3 grid(HWN / 128, DIM / 64, BATCH);
        sgemm_k<<<grid, 256>>>(M, v_s, out, DIM, HWN,
                               (size_t)DIM * DIM, (size_t)DIM * HWN, (size_t)DIM * HWN);
    }
}

// round 4
// speedup vs baseline: 1.6941x; 1.6941x over previous
#include <cuda_runtime.h>
#include <cuda_bf16.h>
#include <math.h>
#include <stdint.h>

// ---------------------------------------------------------------------------
// Problem shapes (fixed)
// ---------------------------------------------------------------------------
#define BATCH 4
#define DIM 192
#define HEADS 8
#define HDIM 24
#define HH 256
#define WW 256
#define HWN 65536
#define QKV_CH 576

#define KEXT 576                     // 3 regions x 192 bf16 slots
#define WROW 288                     // u32 words per extended weight row
#define WCHUNKE (192 * WROW)         // u32 words per 192-row weight chunk

// ---------------------------------------------------------------------------
// Scratch (device globals: allocation-free rule)
// ---------------------------------------------------------------------------
__device__ float g_qkv[(size_t)BATCH * QKV_CH * HWN];
__device__ float g_v[(size_t)BATCH * DIM * HWN];
__device__ float g_spart[(size_t)BATCH * HEADS * 512 * 624];
__device__ float g_sred[BATCH * HEADS * 624];
__device__ float g_attn[BATCH * HEADS * HDIM * HDIM];
__device__ uint32_t g_wext[3 * WCHUNKE];        // qkv weights, 3-term ext rows
__device__ uint32_t g_Mext[BATCH * WCHUNKE];    // proj*blockdiag(attn), ext rows

// ---------------------------------------------------------------------------
// helpers
// ---------------------------------------------------------------------------
__device__ __forceinline__ void split_bf16(float v, uint16_t& h, uint16_t& l) {
    __nv_bfloat16 bh = __float2bfloat16(v);
    float r = v - __bfloat162float(bh);
    __nv_bfloat16 bl = __float2bfloat16(r);
    h = __bfloat16_as_ushort(bh);
    l = __bfloat16_as_ushort(bl);
}

__device__ __forceinline__ void mma16816(float* c, const uint32_t* a, const uint32_t* b) {
    asm volatile(
        "mma.sync.aligned.m16n8k16.row.col.f32.bf16.bf16.f32 "
        "{%0,%1,%2,%3}, {%4,%5,%6,%7}, {%8,%9}, {%0,%1,%2,%3};"
        : "+f"(c[0]), "+f"(c[1]), "+f"(c[2]), "+f"(c[3])
        : "r"(a[0]), "r"(a[1]), "r"(a[2]), "r"(a[3]), "r"(b[0]), "r"(b[1]));
}

// ---------------------------------------------------------------------------
// K0: split qkv weights -> extended bf16 rows [576 rows][576 slots]
// slot k = hi, 192+k = lo, 384+k = hi
// ---------------------------------------------------------------------------
__global__ __launch_bounds__(256)
void wprep_k(const float* __restrict__ w, uint32_t* __restrict__ wext)
{
    int idx = blockIdx.x * 256 + threadIdx.x;
    if (idx >= QKV_CH * DIM) return;
    int r = idx / DIM, k = idx % DIM;
    uint16_t h, l;
    split_bf16(w[idx], h, l);
    uint16_t* row = (uint16_t*)wext + (size_t)r * KEXT;
    row[k] = h;
    row[192 + k] = l;
    row[384 + k] = h;
}

// ---------------------------------------------------------------------------
// tgemm: C[m][px] = sum_c W[m][c] * src[c][px], mma.sync bf16 3-term split.
// Block: 512 threads (16 warps, 4x4), BM=192, BN=128 pixels, K_ext=576.
// B (pixel tile) converted ONCE to resident SMEM hi/lo; A slabs streamed.
// ---------------------------------------------------------------------------
#define AS_STR 20
#define BS_STR 100
#define TGEMM_SMEM ((192 * AS_STR + 2 * 128 * BS_STR) * 4)   // 117760 B

__global__ __launch_bounds__(512, 1)
void tgemm_k(const uint32_t* __restrict__ wext, const float* __restrict__ src,
             float* __restrict__ out, size_t wBS, size_t srcBS, size_t outBS)
{
    extern __shared__ uint32_t dsm[];
    uint32_t* As   = dsm;                        // [192][AS_STR]
    uint32_t* Bs_h = dsm + 192 * AS_STR;         // [128 px][BS_STR] (96 used)
    uint32_t* Bs_l = Bs_h + 128 * BS_STR;

    const int tid = threadIdx.x;
    const int wid = tid >> 5;
    const int lane = tid & 31;
    const int g = lane >> 2;
    const int tig = lane & 3;
    const int warpM = wid & 3;
    const int warpN = wid >> 2;

    const int p0 = blockIdx.x * 128;
    const int chunk = blockIdx.y;
    const int b = blockIdx.z;

    const uint32_t* wp = wext + (size_t)chunk * WCHUNKE + (size_t)b * wBS;
    const float* sp = src + (size_t)b * srcBS + p0;

    // ---- phase 1: convert pixel tile -> resident Bs_h / Bs_l
    // thread: cpair = pass*16 + wid (channels 2cpair, 2cpair+1), px = lane + 32i
#pragma unroll
    for (int pass = 0; pass < 6; pass++) {
        int cpair = pass * 16 + wid;
        const float* r0 = sp + ((size_t)(2 * cpair) << 16);
        const float* r1 = sp + ((size_t)(2 * cpair + 1) << 16);
#pragma unroll
        for (int i = 0; i < 4; i++) {
            int px = lane + 32 * i;
            uint16_t h0, l0, h1, l1;
            split_bf16(__ldg(r0 + px), h0, l0);
            split_bf16(__ldg(r1 + px), h1, l1);
            Bs_h[px * BS_STR + cpair] = (uint32_t)h1 << 16 | h0;
            Bs_l[px * BS_STR + cpair] = (uint32_t)l1 << 16 | l0;
        }
    }

    float acc[3][4][4];
#pragma unroll
    for (int mt = 0; mt < 3; mt++)
#pragma unroll
        for (int nt = 0; nt < 4; nt++)
#pragma unroll
            for (int i = 0; i < 4; i++) acc[mt][nt][i] = 0.f;

    // A slab loader indices (192 rows x 16 u32 per slab)
    const int aM0 = tid >> 2;                  // 0..127
    const int aM1 = 128 + (tid >> 2);          // tid<256 -> 128..191
    const int aJ = (tid & 3) * 4;

    uint4 apf0, apf1;
    apf0 = *(const uint4*)(wp + (size_t)aM0 * WROW + aJ);
    if (tid < 256) apf1 = *(const uint4*)(wp + (size_t)aM1 * WROW + aJ);
    __syncthreads();   // Bs ready

    for (int it = 0; it < 18; it++) {
        // store A slab
        *(uint4*)&As[aM0 * AS_STR + aJ] = apf0;
        if (tid < 256) *(uint4*)&As[aM1 * AS_STR + aJ] = apf1;
        __syncthreads();

        // prefetch next slab
        if (it < 17) {
            const uint32_t* wpn = wp + (it + 1) * 16;
            apf0 = *(const uint4*)(wpn + (size_t)aM0 * WROW + aJ);
            if (tid < 256) apf1 = *(const uint4*)(wpn + (size_t)aM1 * WROW + aJ);
        }

        const uint32_t* BsR = (it < 12) ? Bs_h : Bs_l;
        const int bbase = (it % 6) * 16;

#pragma unroll
        for (int ks = 0; ks < 2; ks++) {
            const int kc = ks * 8;
            uint32_t afr[3][4], bfr[4][2];
#pragma unroll
            for (int mt = 0; mt < 3; mt++) {
                int r0 = warpM * 48 + mt * 16 + g;
                afr[mt][0] = As[r0 * AS_STR + kc + tig];
                afr[mt][1] = As[(r0 + 8) * AS_STR + kc + tig];
                afr[mt][2] = As[r0 * AS_STR + kc + 4 + tig];
                afr[mt][3] = As[(r0 + 8) * AS_STR + kc + 4 + tig];
            }
#pragma unroll
            for (int nt = 0; nt < 4; nt++) {
                int n = warpN * 32 + nt * 8 + g;
                bfr[nt][0] = BsR[n * BS_STR + bbase + kc + tig];
                bfr[nt][1] = BsR[n * BS_STR + bbase + kc + 4 + tig];
            }
#pragma unroll
            for (int mt = 0; mt < 3; mt++)
#pragma unroll
                for (int nt = 0; nt < 4; nt++)
                    mma16816(acc[mt][nt], afr[mt], bfr[nt]);
        }
        __syncthreads();
    }

    // ---- epilogue
    float* op = out + (size_t)b * outBS + ((size_t)chunk * 192 << 16);
#pragma unroll
    for (int mt = 0; mt < 3; mt++) {
#pragma unroll
        for (int nt = 0; nt < 4; nt++) {
            int row = warpM * 48 + mt * 16 + g;
            int col = p0 + warpN * 32 + nt * 8 + tig * 2;
            *(float2*)&op[((size_t)row << 16) + col] =
                make_float2(acc[mt][nt][0], acc[mt][nt][1]);
            *(float2*)&op[((size_t)(row + 8) << 16) + col] =
                make_float2(acc[mt][nt][2], acc[mt][nt][3]);
        }
    }
}

// ---------------------------------------------------------------------------
// depthwise 3x3, SAME padding
// ---------------------------------------------------------------------------
__device__ __forceinline__ float dw3x3(const float* __restrict__ in,
                                       const float* __restrict__ w9,
                                       int y, int x)
{
    float s = 0.f;
#pragma unroll
    for (int dy = -1; dy <= 1; dy++) {
        int yy = y + dy;
        if (yy < 0 || yy > HH - 1) continue;
#pragma unroll
        for (int dx = -1; dx <= 1; dx++) {
            int xx = x + dx;
            if (xx < 0 || xx > WW - 1) continue;
            s = fmaf(w9[(dy + 1) * 3 + (dx + 1)], in[yy * WW + xx], s);
        }
    }
    return s;
}

// ---------------------------------------------------------------------------
// K2: fused dwconv (q,k) + Gram partials + norms
// ---------------------------------------------------------------------------
__global__ __launch_bounds__(192)
void dwgram_k(const float* __restrict__ qkv, const float* __restrict__ dww,
              float* __restrict__ spart)
{
    __shared__ float qs[24][132];
    __shared__ float ks[24][132];

    const int b = blockIdx.z, h = blockIdx.y;
    const int y = blockIdx.x >> 1;
    const int x0 = (blockIdx.x & 1) * 128;
    const int tid = threadIdx.x;

    for (int idx = tid; idx < 48 * 128; idx += 192) {
        int c = idx >> 7;
        int x = idx & 127;
        int ch = (c < 24) ? (h * 24 + c) : (192 + h * 24 + (c - 24));
        const float* in = qkv + ((size_t)(b * QKV_CH + ch) << 16);
        float v = dw3x3(in, dww + ch * 9, y, x0 + x);
        if (c < 24) qs[c][x] = v;
        else        ks[c - 24][x] = v;
    }
    __syncthreads();

    float* out = spart + ((size_t)(b * HEADS + h) * 512 + blockIdx.x) * 624;

    if (tid < 144) {
        int d = (tid / 12) * 2, e = (tid % 12) * 2;
        float a00 = 0, a01 = 0, a10 = 0, a11 = 0;
#pragma unroll 4
        for (int n = 0; n < 128; n++) {
            float q0 = qs[d][n], q1 = qs[d + 1][n];
            float k0 = ks[e][n], k1 = ks[e + 1][n];
            a00 = fmaf(q0, k0, a00); a01 = fmaf(q0, k1, a01);
            a10 = fmaf(q1, k0, a10); a11 = fmaf(q1, k1, a11);
        }
        out[d * 24 + e] = a00;
        out[d * 24 + e + 1] = a01;
        out[(d + 1) * 24 + e] = a10;
        out[(d + 1) * 24 + e + 1] = a11;
    } else if (tid < 168) {
        int d = tid - 144;
        float s = 0;
#pragma unroll 4
        for (int n = 0; n < 128; n++) { float q = qs[d][n]; s = fmaf(q, q, s); }
        out[576 + d] = s;
    } else {
        int e = tid - 168;
        float s = 0;
#pragma unroll 4
        for (int n = 0; n < 128; n++) { float q = ks[e][n]; s = fmaf(q, q, s); }
        out[600 + e] = s;
    }
}

// ---------------------------------------------------------------------------
// K3: dwconv for v channels
// ---------------------------------------------------------------------------
__global__ __launch_bounds__(256)
void dwv_k(const float* __restrict__ qkv, const float* __restrict__ dww,
           float* __restrict__ v)
{
    const int b = blockIdx.z, c = blockIdx.y, y = blockIdx.x, x = threadIdx.x;
    const int ch = 384 + c;
    const float* in = qkv + ((size_t)(b * QKV_CH + ch) << 16);
    v[((size_t)(b * DIM + c) << 16) + y * WW + x] = dw3x3(in, dww + ch * 9, y, x);
}

// ---------------------------------------------------------------------------
// K4: reduce the 512 Gram partials per (b,head)
// ---------------------------------------------------------------------------
__global__ __launch_bounds__(624)
void reduce_k(const float* __restrict__ spart, float* __restrict__ sred)
{
    const int bh = blockIdx.x;
    const int j = threadIdx.x;
    const float* p = spart + (size_t)bh * 512 * 624 + j;
    float s = 0.f;
    for (int y = 0; y < 512; y++) s += p[(size_t)y * 624];
    sred[bh * 624 + j] = s;
}

// ---------------------------------------------------------------------------
// K5: softmax
// ---------------------------------------------------------------------------
__global__ __launch_bounds__(576)
void softmax_k(const float* __restrict__ sred, const float* __restrict__ temp,
               float* __restrict__ attn)
{
    const int bh = blockIdx.x;
    const int h = bh & 7;
    const int t = threadIdx.x;
    const int d = t / 24, e = t % 24;

    __shared__ float lg[24][24];
    __shared__ float rmax[24], rsum[24];

    const float* S = sred + bh * 624;
    float nq = fmaxf(sqrtf(S[576 + d]), 1e-12f);
    float nk = fmaxf(sqrtf(S[600 + e]), 1e-12f);
    float l = S[d * 24 + e] / (nq * nk) * temp[h];
    lg[d][e] = l;
    __syncthreads();

    if (e == 0) {
        float m = -1e30f;
        for (int j = 0; j < 24; j++) m = fmaxf(m, lg[d][j]);
        rmax[d] = m;
    }
    __syncthreads();
    float ex = expf(l - rmax[d]);
    lg[d][e] = ex;
    __syncthreads();
    if (e == 0) {
        float s = 0.f;
        for (int j = 0; j < 24; j++) s += lg[d][j];
        rsum[d] = s;
    }
    __syncthreads();
    attn[bh * 576 + d * 24 + e] = ex / rsum[d];
}

// ---------------------------------------------------------------------------
// K6: M[b] = P * blockdiag(attn[b]) -> extended bf16 rows
// ---------------------------------------------------------------------------
__global__ __launch_bounds__(256)
void buildM_k(const float* __restrict__ attn, const float* __restrict__ P,
              uint32_t* __restrict__ Mext)
{
    const int b = blockIdx.x;
    __shared__ float at[HEADS * 576];
    for (int i = threadIdx.x; i < HEADS * 576; i += 256) at[i] = attn[b * HEADS * 576 + i];
    __syncthreads();

    for (int idx = threadIdx.x; idx < DIM * DIM; idx += 256) {
        int o = idx / DIM, c = idx % DIM;
        int hh = c / 24, e = c % 24;
        float s = 0.f;
#pragma unroll
        for (int d = 0; d < 24; d++)
            s = fmaf(P[o * DIM + hh * 24 + d], at[hh * 576 + d * 24 + e], s);
        uint16_t h, l;
        split_bf16(s, h, l);
        uint16_t* row = (uint16_t*)(Mext + (size_t)b * WCHUNKE) + (size_t)o * KEXT;
        row[c] = h;
        row[192 + c] = l;
        row[384 + c] = h;
    }
}

// ---------------------------------------------------------------------------
// launch
// ---------------------------------------------------------------------------
extern "C" void kernel_launch(void* const* d_in, const int* in_sizes, int n_in,
                              void* d_out, int out_size)
{
    const float* x      = (const float*)d_in[0];
    const float* qkv_w  = (const float*)d_in[1];
    const float* dw_w   = (const float*)d_in[2];
    const float* proj_w = (const float*)d_in[3];
    const float* temp   = (const float*)d_in[4];
    float* out = (float*)d_out;

    float *qkv_s, *v_s, *spart, *sred, *attn;
    uint32_t *wext, *Mext;
    cudaGetSymbolAddress((void**)&qkv_s, g_qkv);
    cudaGetSymbolAddress((void**)&v_s,   g_v);
    cudaGetSymbolAddress((void**)&spart, g_spart);
    cudaGetSymbolAddress((void**)&sred,  g_sred);
    cudaGetSymbolAddress((void**)&attn,  g_attn);
    cudaGetSymbolAddress((void**)&wext,  g_wext);
    cudaGetSymbolAddress((void**)&Mext,  g_Mext);

    cudaFuncSetAttribute(tgemm_k, cudaFuncAttributeMaxDynamicSharedMemorySize,
                         TGEMM_SMEM);

    // K0: weight split/extend
    wprep_k<<<(QKV_CH * DIM + 255) / 256, 256>>>(qkv_w, wext);

    // K1: qkv = W_qkv @ x  (tensor-core 3-term split, 3 chunks of 192 rows)
    {
        dim3 grid(HWN / 128, 3, BATCH);
        tgemm_k<<<grid, 512, TGEMM_SMEM>>>(wext, x, qkv_s, 0,
                                           (size_t)DIM * HWN, (size_t)QKV_CH * HWN);
    }
    // K2: fused dwconv(q,k) + Gram partials
    {
        dim3 grid(512, HEADS, BATCH);
        dwgram_k<<<grid, 192>>>(qkv_s, dw_w, spart);
    }
    // K3: dwconv(v)
    {
        dim3 grid(HH, DIM, BATCH);
        dwv_k<<<grid, 256>>>(qkv_s, dw_w, v_s);
    }
    // K4: reduce Gram partials
    reduce_k<<<BATCH * HEADS, 624>>>(spart, sred);
    // K5: softmax
    softmax_k<<<BATCH * HEADS, 576>>>(sred, temp, attn);
    // K6: M = P * blockdiag(attn) -> extended bf16
    buildM_k<<<BATCH, 256>>>(attn, proj_w, Mext);
    // K7: out = M @ V (fused attn*V + projection)
    {
        dim3 grid(HWN / 128, 1, BATCH);
        tgemm_k<<<grid, 512, TGEMM_SMEM>>>(Mext, v_s, out, WCHUNKE,
                                           (size_t)DIM * HWN, (size_t)DIM * HWN);
    }
}